// round 15
// baseline (speedup 1.0000x reference)
#include <cuda_runtime.h>
#include <cuda_bf16.h>
#include <cstdint>

// Dynamics_40510131536026: LSTM encoder (T=64) + autoregressive decoder (T=64)
// B=65536, HID=32, fp32.
// R15: quad-split. Each batch element is handled by 4 consecutive lanes; lane
// q computes gate rows [8q, 8q+8). Full h replicated per lane (h2[16] packed
// f32x2); new h exchanged at step end with a 2-stage shfl butterfly. This
// quarters per-thread work/registers -> 4 CTAs/SM (16 warps, 2x R13's warp
// supply), attacking the measured stall-bound wall (issue=50%, fma=49% @ 2
// warps/SMSP). Weights in smem with a 16B per-q skew (q-stride 4112B) so the
// 4 distinct row addresses per LDS wavefront hit disjoint banks.
// FFMA2 (fma.rn.f32x2) packed over K; j loop unroll-1 (R11: full unroll ->
// ptxas load hoisting -> catastrophic spill).

#define THREADS 128
#define HID 32
#define T_ENC 64

typedef unsigned long long u64;

__device__ __forceinline__ u64 fma2(u64 a, u64 b, u64 c) {
    u64 d;
    asm("fma.rn.f32x2 %0, %1, %2, %3;" : "=l"(d) : "l"(a), "l"(b), "l"(c));
    return d;
}
__device__ __forceinline__ u64 pack2(float lo, float hi) {
    u64 r;
    asm("mov.b64 %0, {%1, %2};" : "=l"(r) : "f"(lo), "f"(hi));
    return r;
}
__device__ __forceinline__ float hsum2(u64 v) {
    float lo, hi;
    asm("mov.b64 {%0, %1}, %2;" : "=f"(lo), "=f"(hi) : "l"(v));
    return lo + hi;
}
__device__ __forceinline__ float sigm(float x) {
    return __fdividef(1.0f, 1.0f + __expf(-x));
}
__device__ __forceinline__ float tanhx(float x) {
    return __fdividef(2.0f, 1.0f + __expf(-2.0f * x)) - 1.0f;
}

// Skewed weight regions: per-q stride includes +16B so the 4 lane addresses of
// one wavefront land in distinct bank groups (4112/4 mod 32 = 4).
#define WHH_QSTRIDE 4112   // 8 rows * 512B + 16B skew
#define WIH_QSTRIDE 528    // 8 rows * 64B  + 16B skew

__global__ __launch_bounds__(THREADS, 4)
void dynamics_kernel(
    const float* __restrict__ poses,   // [64, B, 4]
    const float* __restrict__ W_ih,    // [128, 4]
    const float* __restrict__ W_hh,    // [128, 32]
    const float* __restrict__ W_d,     // [3, 32]
    const int*   __restrict__ n_new,   // scalar
    float* __restrict__ out,           // [Tdec, B, 4]
    int B, int Tdec_max)
{
    // Static smem, ~27 KB total.
    __shared__ __align__(16) char sWhh[4 * WHH_QSTRIDE];  // 16448 B
    __shared__ __align__(16) char sWih[4 * WIH_QSTRIDE];  //  2112 B
    __shared__ __align__(16) float4 sWd[16];              //   256 B
    __shared__ u64   sHn[4 * THREADS];                    //  4096 B (hn pair staging)
    __shared__ float sC [8 * THREADS];                    //  4096 B (c state, 8 rows/lane)

    const int tid = threadIdx.x;

    // ---- Cooperative weight packing ----
    // sWhh region q, row jj (global j = 8q+jj), entry (k2, e):
    //   offset = q*4112 + jj*512 + k2*32 + e*16
    //   e=0 -> {Wi[j][k],Wi[j][k+1],Wf[j][k],Wf[j][k+1]}, e=1 -> {Wg...,Wo...}
    for (int idx = tid; idx < 4 * 8 * 16 * 2; idx += THREADS) {
        int e  = idx & 1;
        int k2 = (idx >> 1) & 15;
        int jj = (idx >> 5) & 7;
        int q  = idx >> 8;
        int j  = q * 8 + jj;
        int g0 = 2 * e, g1 = 2 * e + 1;
        int k  = 2 * k2;
        *reinterpret_cast<float4*>(sWhh + q * WHH_QSTRIDE + jj * 512 + k2 * 32 + e * 16) =
            make_float4(
                W_hh[(g0 * HID + j) * HID + k], W_hh[(g0 * HID + j) * HID + k + 1],
                W_hh[(g1 * HID + j) * HID + k], W_hh[(g1 * HID + j) * HID + k + 1]);
    }
    // sWih region q, row jj, entry (half, e): offset = q*528 + jj*64 + half*32 + e*16
    for (int idx = tid; idx < 4 * 8 * 2 * 2; idx += THREADS) {
        int e    = idx & 1;
        int half = (idx >> 1) & 1;
        int jj   = (idx >> 2) & 7;
        int q    = idx >> 5;
        int j    = q * 8 + jj;
        int g0 = 2 * e, g1 = 2 * e + 1;
        int m  = 2 * half;
        *reinterpret_cast<float4*>(sWih + q * WIH_QSTRIDE + jj * 64 + half * 32 + e * 16) =
            make_float4(
                W_ih[(g0 * HID + j) * 4 + m], W_ih[(g0 * HID + j) * 4 + m + 1],
                W_ih[(g1 * HID + j) * 4 + m], W_ih[(g1 * HID + j) * 4 + m + 1]);
    }
    for (int idx = tid; idx < 16; idx += THREADS) {
        int k = 2 * idx;   // rows 1 (cs) and 2 (sn) of W_dense
        sWd[idx] = make_float4(W_d[HID + k], W_d[HID + k + 1],
                               W_d[2 * HID + k], W_d[2 * HID + k + 1]);
    }
    __syncthreads();

    const int g    = blockIdx.x * THREADS + tid;
    const int quad = g >> 2;           // element index
    const int q    = g & 3;            // sub-lane within quad
    const bool valid = (quad < B);
    const int b = valid ? quad : (B - 1);   // clamp; stores guarded

    const char* wq = sWhh + q * WHH_QSTRIDE;
    const char* xq = sWih + q * WIH_QSTRIDE;
    const bool qlo1 = (q & 1) == 0;
    const bool qlo2 = (q & 2) == 0;

    u64 h2[16];
#pragma unroll
    for (int k2 = 0; k2 < 16; k2++) h2[k2] = 0ull;
#pragma unroll
    for (int jj = 0; jj < 8; jj++) sC[jj * THREADS + tid] = 0.0f;

    int Td = *n_new;
    if (Td > Tdec_max) Td = Tdec_max;

    float px = 0.f, py = 0.f;   // last pose xy (encoder) / constant (decoder)
    float xc = 0.f, xs = 0.f;   // current input elems 2,3

    // total recurrence: T_ENC encoder steps + (Td-1) decoder LSTM steps.
#pragma unroll 1
    for (int t = 0; t < T_ENC; t++) {
        float4 p = *reinterpret_cast<const float4*>(poses + ((size_t)t * B + b) * 4);
        px = p.x; py = p.y; xc = p.z; xs = p.w;
        u64 x0 = pack2(px, py), x1 = pack2(xc, xs);

        // ---- one LSTM step (rows 8q..8q+7 on this lane) ----
        float hv_prev = 0.0f;
#pragma unroll 1
        for (int jj = 0; jj < 8; jj++) {
            const char* xrow = xq + jj * 64;
            const char* wrow = wq + jj * 512;
            u64 ai, af, ag, ao;
            ulonglong2 w0 = *reinterpret_cast<const ulonglong2*>(xrow);
            ulonglong2 w1 = *reinterpret_cast<const ulonglong2*>(xrow + 16);
            ai = fma2(x0, w0.x, 0ull);
            af = fma2(x0, w0.y, 0ull);
            ag = fma2(x0, w1.x, 0ull);
            ao = fma2(x0, w1.y, 0ull);
            w0 = *reinterpret_cast<const ulonglong2*>(xrow + 32);
            w1 = *reinterpret_cast<const ulonglong2*>(xrow + 48);
            ai = fma2(x1, w0.x, ai);
            af = fma2(x1, w0.y, af);
            ag = fma2(x1, w1.x, ag);
            ao = fma2(x1, w1.y, ao);
#pragma unroll
            for (int k2 = 0; k2 < 16; k2++) {
                w0 = *reinterpret_cast<const ulonglong2*>(wrow + k2 * 32);
                w1 = *reinterpret_cast<const ulonglong2*>(wrow + k2 * 32 + 16);
                u64 h = h2[k2];
                ai = fma2(h, w0.x, ai);
                af = fma2(h, w0.y, af);
                ag = fma2(h, w1.x, ag);
                ao = fma2(h, w1.y, ao);
            }
            float ii = sigm(hsum2(ai));
            float ff = sigm(hsum2(af));
            float gg = tanhx(hsum2(ag));
            float oo = sigm(hsum2(ao));
            float cn = ff * sC[jj * THREADS + tid] + ii * gg;
            sC[jj * THREADS + tid] = cn;
            float hj = oo * tanhx(cn);
            if (jj & 1) sHn[(jj >> 1) * THREADS + tid] = pack2(hv_prev, hj);
            else        hv_prev = hj;
        }
        // ---- butterfly h exchange: quad lanes -> full h2[16] each ----
        u64 own0 = sHn[0 * THREADS + tid], own1 = sHn[1 * THREADS + tid];
        u64 own2 = sHn[2 * THREADS + tid], own3 = sHn[3 * THREADS + tid];
        u64 p0 = __shfl_xor_sync(0xffffffffu, own0, 1);
        u64 p1 = __shfl_xor_sync(0xffffffffu, own1, 1);
        u64 p2 = __shfl_xor_sync(0xffffffffu, own2, 1);
        u64 p3 = __shfl_xor_sync(0xffffffffu, own3, 1);
        u64 hf[8];
        hf[0] = qlo1 ? own0 : p0;  hf[1] = qlo1 ? own1 : p1;
        hf[2] = qlo1 ? own2 : p2;  hf[3] = qlo1 ? own3 : p3;
        hf[4] = qlo1 ? p0 : own0;  hf[5] = qlo1 ? p1 : own1;
        hf[6] = qlo1 ? p2 : own2;  hf[7] = qlo1 ? p3 : own3;
        u64 ot[8];
#pragma unroll
        for (int m = 0; m < 8; m++) ot[m] = __shfl_xor_sync(0xffffffffu, hf[m], 2);
#pragma unroll
        for (int m = 0; m < 8; m++) {
            h2[m]     = qlo2 ? hf[m] : ot[m];
            h2[8 + m] = qlo2 ? ot[m] : hf[m];
        }
    }

    // ---- Decoder ----
#pragma unroll 1
    for (int t = 0; t < Td; t++) {
        // vel components 1 (cs) and 2 (sn) — all 4 lanes compute redundantly
        u64 ac = 0ull, as = 0ull;
#pragma unroll
        for (int k2 = 0; k2 < 16; k2++) {
            ulonglong2 w = *reinterpret_cast<const ulonglong2*>(&sWd[k2]);
            ac = fma2(h2[k2], w.x, ac);
            as = fma2(h2[k2], w.y, as);
        }
        float cs = hsum2(ac);
        float sn = hsum2(as);
        float rn;
        asm("rsqrt.approx.f32 %0, %1;" : "=f"(rn) : "f"(cs * cs + sn * sn));
        cs *= rn;
        sn *= rn;

        if (q == 0 && valid)
            *reinterpret_cast<float4*>(out + ((size_t)t * B + b) * 4) =
                make_float4(px, py, cs, sn);

        if (t + 1 < Td) {  // last step's LSTM output is never consumed
            u64 x0 = pack2(px, py), x1 = pack2(cs, sn);
            float hv_prev = 0.0f;
#pragma unroll 1
            for (int jj = 0; jj < 8; jj++) {
                const char* xrow = xq + jj * 64;
                const char* wrow = wq + jj * 512;
                u64 ai, af, ag, ao;
                ulonglong2 w0 = *reinterpret_cast<const ulonglong2*>(xrow);
                ulonglong2 w1 = *reinterpret_cast<const ulonglong2*>(xrow + 16);
                ai = fma2(x0, w0.x, 0ull);
                af = fma2(x0, w0.y, 0ull);
                ag = fma2(x0, w1.x, 0ull);
                ao = fma2(x0, w1.y, 0ull);
                w0 = *reinterpret_cast<const ulonglong2*>(xrow + 32);
                w1 = *reinterpret_cast<const ulonglong2*>(xrow + 48);
                ai = fma2(x1, w0.x, ai);
                af = fma2(x1, w0.y, af);
                ag = fma2(x1, w1.x, ag);
                ao = fma2(x1, w1.y, ao);
#pragma unroll
                for (int k2 = 0; k2 < 16; k2++) {
                    w0 = *reinterpret_cast<const ulonglong2*>(wrow + k2 * 32);
                    w1 = *reinterpret_cast<const ulonglong2*>(wrow + k2 * 32 + 16);
                    u64 h = h2[k2];
                    ai = fma2(h, w0.x, ai);
                    af = fma2(h, w0.y, af);
                    ag = fma2(h, w1.x, ag);
                    ao = fma2(h, w1.y, ao);
                }
                float ii = sigm(hsum2(ai));
                float ff = sigm(hsum2(af));
                float gg = tanhx(hsum2(ag));
                float oo = sigm(hsum2(ao));
                float cn = ff * sC[jj * THREADS + tid] + ii * gg;
                sC[jj * THREADS + tid] = cn;
                float hj = oo * tanhx(cn);
                if (jj & 1) sHn[(jj >> 1) * THREADS + tid] = pack2(hv_prev, hj);
                else        hv_prev = hj;
            }
            u64 own0 = sHn[0 * THREADS + tid], own1 = sHn[1 * THREADS + tid];
            u64 own2 = sHn[2 * THREADS + tid], own3 = sHn[3 * THREADS + tid];
            u64 p0 = __shfl_xor_sync(0xffffffffu, own0, 1);
            u64 p1 = __shfl_xor_sync(0xffffffffu, own1, 1);
            u64 p2 = __shfl_xor_sync(0xffffffffu, own2, 1);
            u64 p3 = __shfl_xor_sync(0xffffffffu, own3, 1);
            u64 hf[8];
            hf[0] = qlo1 ? own0 : p0;  hf[1] = qlo1 ? own1 : p1;
            hf[2] = qlo1 ? own2 : p2;  hf[3] = qlo1 ? own3 : p3;
            hf[4] = qlo1 ? p0 : own0;  hf[5] = qlo1 ? p1 : own1;
            hf[6] = qlo1 ? p2 : own2;  hf[7] = qlo1 ? p3 : own3;
            u64 ot[8];
#pragma unroll
            for (int m = 0; m < 8; m++) ot[m] = __shfl_xor_sync(0xffffffffu, hf[m], 2);
#pragma unroll
            for (int m = 0; m < 8; m++) {
                h2[m]     = qlo2 ? hf[m] : ot[m];
                h2[8 + m] = qlo2 ? ot[m] : hf[m];
            }
        }
    }
}

extern "C" void kernel_launch(void* const* d_in, const int* in_sizes, int n_in,
                              void* d_out, int out_size) {
    const float* poses = (const float*)d_in[0];
    // d_in[1] = deltas: never read (the scan body ignores dt); only its length matters.
    const float* W_ih  = (const float*)d_in[2];
    const float* W_hh  = (const float*)d_in[3];
    const float* W_d   = (const float*)d_in[4];
    const int*   n_new = (const int*)d_in[5];
    float* out = (float*)d_out;

    int B = in_sizes[1] / 64;                      // deltas is [64, B]
    int Tdec_max = (B > 0) ? (out_size / (4 * B)) : 0;

    long long total_threads = 4LL * B;             // 4 lanes per element
    int grid = (int)((total_threads + THREADS - 1) / THREADS);   // 2048 for B=65536
    dynamics_kernel<<<grid, THREADS>>>(
        poses, W_ih, W_hh, W_d, n_new, out, B, Tdec_max);
}

// round 16
// speedup vs baseline: 1.3602x; 1.3602x over previous
#include <cuda_runtime.h>
#include <cuda_bf16.h>
#include <cstdint>

// Dynamics_40510131536026: LSTM encoder (T=64) + autoregressive decoder (T=64)
// B=65536, HID=32, fp32. Two batch elements per thread (crossbar-return law:
// per-element smem weight cost ~ 1/(elems per thread); 2/thread co-saturates
// crossbar (~1.07ms floor) and fma (~1.12ms floor)).
// R16: (a) THREADS=256, grid=128 -> perfectly balanced 8 warps / 512 elem per
// busy SM (R13's wall was 40 SMs stuck at 1 warp/SMSP); (b) modulo-2 software
// pipeline: accumulator sets aE/aO alternate so epi(j) issues after
// fma_block(j+1) with ZERO rotation movs (R14's mov tax); (c) encoder pose
// prefetch. FFMA2 packed over K; weights broadcast from smem; j-loop kept
// short-bodied (R11: big straight-line body -> ptxas hoist -> spill).

#define THREADS 256
#define HID 32
#define T_ENC 64

typedef unsigned long long u64;

__device__ __forceinline__ u64 fma2(u64 a, u64 b, u64 c) {
    u64 d;
    asm("fma.rn.f32x2 %0, %1, %2, %3;" : "=l"(d) : "l"(a), "l"(b), "l"(c));
    return d;
}
__device__ __forceinline__ u64 pack2(float lo, float hi) {
    u64 r;
    asm("mov.b64 %0, {%1, %2};" : "=l"(r) : "f"(lo), "f"(hi));
    return r;
}
__device__ __forceinline__ float hsum2(u64 v) {
    float lo, hi;
    asm("mov.b64 {%0, %1}, %2;" : "=f"(lo), "=f"(hi) : "l"(v));
    return lo + hi;
}
__device__ __forceinline__ float sigm(float x) {
    return __fdividef(1.0f, 1.0f + __expf(-x));
}
__device__ __forceinline__ float tanhx(float x) {
    return __fdividef(2.0f, 1.0f + __expf(-2.0f * x)) - 1.0f;
}

// Dynamic smem layout:
//   sWhh : 32*16*2 float4 = 16384 B
//   sWih : 32*2*2  float4 =  2048 B
//   sWd  : 16      float4 =   256 B
//   sHnA/sHnB : 16*256 u64  = 32768 B each   (h_new staging, per-thread slot)
//   sCa/sCb   : 32*256 f32  = 32768 B each   (c state, per-thread slot)
// total = 149.8 KB  (fits the 227 KB dynamic-smem cap, 1 CTA/SM)
#define SWHH_F4 (HID * 16 * 2)
#define SWIH_F4 (HID * 2 * 2)
#define SWD_F4  16
#define SMEM_BYTES ((SWHH_F4 + SWIH_F4 + SWD_F4) * 16 \
                    + 2 * 16 * THREADS * 8 + 2 * HID * THREADS * 4)

// FMA/LDS block for gate-row j, both elements. acc[0..3] = i,f,g,o elem A;
// acc[4..7] elem B.
__device__ __forceinline__ void fma_block(
    int j, u64 x0a, u64 x1a, u64 x0b, u64 x1b,
    const u64* __restrict__ h2a, const u64* __restrict__ h2b,
    const float4* __restrict__ sWih, const float4* __restrict__ sWhh,
    u64* __restrict__ acc)
{
    {   // x @ W_ih.T contribution (weights loaded once, used for both elems)
        ulonglong2 w0 = *reinterpret_cast<const ulonglong2*>(&sWih[(j * 2 + 0) * 2]);
        ulonglong2 w1 = *reinterpret_cast<const ulonglong2*>(&sWih[(j * 2 + 0) * 2 + 1]);
        acc[0] = fma2(x0a, w0.x, 0ull);  acc[4] = fma2(x0b, w0.x, 0ull);
        acc[1] = fma2(x0a, w0.y, 0ull);  acc[5] = fma2(x0b, w0.y, 0ull);
        acc[2] = fma2(x0a, w1.x, 0ull);  acc[6] = fma2(x0b, w1.x, 0ull);
        acc[3] = fma2(x0a, w1.y, 0ull);  acc[7] = fma2(x0b, w1.y, 0ull);
        w0 = *reinterpret_cast<const ulonglong2*>(&sWih[(j * 2 + 1) * 2]);
        w1 = *reinterpret_cast<const ulonglong2*>(&sWih[(j * 2 + 1) * 2 + 1]);
        acc[0] = fma2(x1a, w0.x, acc[0]);  acc[4] = fma2(x1b, w0.x, acc[4]);
        acc[1] = fma2(x1a, w0.y, acc[1]);  acc[5] = fma2(x1b, w0.y, acc[5]);
        acc[2] = fma2(x1a, w1.x, acc[2]);  acc[6] = fma2(x1b, w1.x, acc[6]);
        acc[3] = fma2(x1a, w1.y, acc[3]);  acc[7] = fma2(x1b, w1.y, acc[7]);
    }
    const float4* wrow = &sWhh[j * 16 * 2];
#pragma unroll
    for (int k2 = 0; k2 < 16; k2++) {
        ulonglong2 w0 = *reinterpret_cast<const ulonglong2*>(&wrow[k2 * 2]);
        ulonglong2 w1 = *reinterpret_cast<const ulonglong2*>(&wrow[k2 * 2 + 1]);
        u64 ha = h2a[k2];
        u64 hb = h2b[k2];
        acc[0] = fma2(ha, w0.x, acc[0]);  acc[4] = fma2(hb, w0.x, acc[4]);
        acc[1] = fma2(ha, w0.y, acc[1]);  acc[5] = fma2(hb, w0.y, acc[5]);
        acc[2] = fma2(ha, w1.x, acc[2]);  acc[6] = fma2(hb, w1.x, acc[6]);
        acc[3] = fma2(ha, w1.y, acc[3]);  acc[7] = fma2(hb, w1.y, acc[7]);
    }
}

// Activation epilogue for gate-row j (consumes acc of row j), both elements.
__device__ __forceinline__ void epi(
    int j, const u64* __restrict__ acc, float& hva, float& hvb,
    float* __restrict__ sCa, float* __restrict__ sCb,
    u64* __restrict__ sHnA, u64* __restrict__ sHnB, int tid)
{
    {   // Element A
        float ii = sigm(hsum2(acc[0]));
        float ff = sigm(hsum2(acc[1]));
        float gg = tanhx(hsum2(acc[2]));
        float oo = sigm(hsum2(acc[3]));
        float cn = ff * sCa[j * THREADS + tid] + ii * gg;
        sCa[j * THREADS + tid] = cn;
        float hj = oo * tanhx(cn);
        if (j & 1) sHnA[(j >> 1) * THREADS + tid] = pack2(hva, hj);
        else       hva = hj;
    }
    {   // Element B
        float ii = sigm(hsum2(acc[4]));
        float ff = sigm(hsum2(acc[5]));
        float gg = tanhx(hsum2(acc[6]));
        float oo = sigm(hsum2(acc[7]));
        float cn = ff * sCb[j * THREADS + tid] + ii * gg;
        sCb[j * THREADS + tid] = cn;
        float hj = oo * tanhx(cn);
        if (j & 1) sHnB[(j >> 1) * THREADS + tid] = pack2(hvb, hj);
        else       hvb = hj;
    }
}

// One LSTM step for two batch elements, modulo-2 pipelined:
//   fma(0)->aE; { fma(2p+1)->aO; epi(2p,aE); fma(2p+2)->aE; epi(2p+1,aO); }
//   fma(31)->aO; epi(30,aE); epi(31,aO).
// Each epi's serial MUFU chain issues behind the NEXT row's fma/LDS stream,
// with no rotation movs (two fixed accumulator sets).
__device__ __forceinline__ void lstm_step2(
    u64 x0a, u64 x1a, u64 x0b, u64 x1b,
    u64* __restrict__ h2a, u64* __restrict__ h2b,
    const float4* __restrict__ sWih, const float4* __restrict__ sWhh,
    u64* __restrict__ sHnA, u64* __restrict__ sHnB,
    float* __restrict__ sCa, float* __restrict__ sCb, int tid)
{
    float hva = 0.0f, hvb = 0.0f;
    u64 aE[8], aO[8];
    fma_block(0, x0a, x1a, x0b, x1b, h2a, h2b, sWih, sWhh, aE);
#pragma unroll 1
    for (int jp = 0; jp < 15; jp++) {
        int j = 2 * jp;
        fma_block(j + 1, x0a, x1a, x0b, x1b, h2a, h2b, sWih, sWhh, aO);
        epi(j, aE, hva, hvb, sCa, sCb, sHnA, sHnB, tid);
        fma_block(j + 2, x0a, x1a, x0b, x1b, h2a, h2b, sWih, sWhh, aE);
        epi(j + 1, aO, hva, hvb, sCa, sCb, sHnA, sHnB, tid);
    }
    fma_block(31, x0a, x1a, x0b, x1b, h2a, h2b, sWih, sWhh, aO);
    epi(30, aE, hva, hvb, sCa, sCb, sHnA, sHnB, tid);
    epi(31, aO, hva, hvb, sCa, sCb, sHnA, sHnB, tid);

#pragma unroll
    for (int k2 = 0; k2 < 16; k2++) {
        h2a[k2] = sHnA[k2 * THREADS + tid];
        h2b[k2] = sHnB[k2 * THREADS + tid];
    }
}

__global__ __launch_bounds__(THREADS, 1)
void dynamics_kernel(
    const float* __restrict__ poses,   // [64, B, 4]
    const float* __restrict__ W_ih,    // [128, 4]
    const float* __restrict__ W_hh,    // [128, 32]
    const float* __restrict__ W_d,     // [3, 32]
    const int*   __restrict__ n_new,   // scalar
    float* __restrict__ out,           // [Tdec, B, 4]
    int B, int Bh, int Tdec_max)
{
    extern __shared__ char smem_raw[];
    float4* sWhh = reinterpret_cast<float4*>(smem_raw);
    float4* sWih = sWhh + SWHH_F4;
    float4* sWd  = sWih + SWIH_F4;
    u64*    sHnA = reinterpret_cast<u64*>(sWd + SWD_F4);
    u64*    sHnB = sHnA + 16 * THREADS;
    float*  sCa  = reinterpret_cast<float*>(sHnB + 16 * THREADS);
    float*  sCb  = sCa + HID * THREADS;

    int tid = threadIdx.x;

    // Cooperative weight packing.
    // sWhh[(j*16+k2)*2+e]: e=0 -> {Wi[j][k],Wi[j][k+1],Wf[j][k],Wf[j][k+1]},
    //                      e=1 -> {Wg..., Wo...}   (gate rows: i=0,f=1,g=2,o=3)
    for (int idx = tid; idx < SWHH_F4; idx += THREADS) {
        int e  = idx & 1;
        int k2 = (idx >> 1) & 15;
        int j  = idx >> 5;
        int g0 = 2 * e, g1 = 2 * e + 1;
        int k  = 2 * k2;
        sWhh[idx] = make_float4(
            W_hh[(g0 * HID + j) * HID + k], W_hh[(g0 * HID + j) * HID + k + 1],
            W_hh[(g1 * HID + j) * HID + k], W_hh[(g1 * HID + j) * HID + k + 1]);
    }
    for (int idx = tid; idx < SWIH_F4; idx += THREADS) {
        int e  = idx & 1;
        int m2 = (idx >> 1) & 1;
        int j  = idx >> 2;
        int g0 = 2 * e, g1 = 2 * e + 1;
        int m  = 2 * m2;
        sWih[idx] = make_float4(
            W_ih[(g0 * HID + j) * 4 + m], W_ih[(g0 * HID + j) * 4 + m + 1],
            W_ih[(g1 * HID + j) * 4 + m], W_ih[(g1 * HID + j) * 4 + m + 1]);
    }
    for (int idx = tid; idx < SWD_F4; idx += THREADS) {
        int k = 2 * idx;   // rows 1 (cs) and 2 (sn) of W_dense
        sWd[idx] = make_float4(W_d[HID + k], W_d[HID + k + 1],
                               W_d[2 * HID + k], W_d[2 * HID + k + 1]);
    }
    __syncthreads();

    int b0 = blockIdx.x * THREADS + tid;
    if (b0 >= Bh) return;
    int b1 = b0 + Bh;
    bool vb = (b1 < B);
    int b1c = vb ? b1 : b0;   // clamp: redundant compute, stores guarded

    u64 h2a[16], h2b[16];
#pragma unroll
    for (int k2 = 0; k2 < 16; k2++) { h2a[k2] = 0ull; h2b[k2] = 0ull; }
#pragma unroll
    for (int j = 0; j < HID; j++) {
        sCa[j * THREADS + tid] = 0.0f;
        sCb[j * THREADS + tid] = 0.0f;
    }

    // ---- Encoder: 64 steps over poses, with next-step pose prefetch ----
    float4 pa = *reinterpret_cast<const float4*>(poses + (size_t)b0 * 4);
    float4 pb = *reinterpret_cast<const float4*>(poses + (size_t)b1c * 4);
#pragma unroll 1
    for (int t = 0; t < T_ENC; t++) {
        float4 na = pa, nb = pb;
        if (t + 1 < T_ENC) {   // prefetch t+1 before the heavy step body
            na = *reinterpret_cast<const float4*>(poses + (((size_t)(t + 1)) * B + b0) * 4);
            nb = *reinterpret_cast<const float4*>(poses + (((size_t)(t + 1)) * B + b1c) * 4);
        }
        lstm_step2(pack2(pa.x, pa.y), pack2(pa.z, pa.w),
                   pack2(pb.x, pb.y), pack2(pb.z, pb.w),
                   h2a, h2b, sWih, sWhh, sHnA, sHnB, sCa, sCb, tid);
        pa = na; pb = nb;
    }
    float pxa = pa.x, pya = pa.y;   // last_pose[:, :2], constant in decoder
    float pxb = pb.x, pyb = pb.y;

    int Td = *n_new;
    if (Td > Tdec_max) Td = Tdec_max;

    // ---- Decoder ----
#pragma unroll 1
    for (int t = 0; t < Td; t++) {
        u64 aca = 0ull, asa = 0ull, acb = 0ull, asb = 0ull;
#pragma unroll
        for (int k2 = 0; k2 < 16; k2++) {
            ulonglong2 w = *reinterpret_cast<const ulonglong2*>(&sWd[k2]);
            aca = fma2(h2a[k2], w.x, aca);  acb = fma2(h2b[k2], w.x, acb);
            asa = fma2(h2a[k2], w.y, asa);  asb = fma2(h2b[k2], w.y, asb);
        }
        float csa = hsum2(aca), sna = hsum2(asa);
        float csb = hsum2(acb), snb = hsum2(asb);
        float rna, rnb;
        asm("rsqrt.approx.f32 %0, %1;" : "=f"(rna) : "f"(csa * csa + sna * sna));
        asm("rsqrt.approx.f32 %0, %1;" : "=f"(rnb) : "f"(csb * csb + snb * snb));
        csa *= rna; sna *= rna;
        csb *= rnb; snb *= rnb;

        *reinterpret_cast<float4*>(out + ((size_t)t * B + b0) * 4) =
            make_float4(pxa, pya, csa, sna);
        if (vb)
            *reinterpret_cast<float4*>(out + ((size_t)t * B + b1) * 4) =
                make_float4(pxb, pyb, csb, snb);

        if (t + 1 < Td) {  // last step's LSTM output is never consumed
            lstm_step2(pack2(pxa, pya), pack2(csa, sna),
                       pack2(pxb, pyb), pack2(csb, snb),
                       h2a, h2b, sWih, sWhh, sHnA, sHnB, sCa, sCb, tid);
        }
    }
}

extern "C" void kernel_launch(void* const* d_in, const int* in_sizes, int n_in,
                              void* d_out, int out_size) {
    const float* poses = (const float*)d_in[0];
    // d_in[1] = deltas: never read (the scan body ignores dt); only its length matters.
    const float* W_ih  = (const float*)d_in[2];
    const float* W_hh  = (const float*)d_in[3];
    const float* W_d   = (const float*)d_in[4];
    const int*   n_new = (const int*)d_in[5];
    float* out = (float*)d_out;

    int B = in_sizes[1] / 64;                      // deltas is [64, B]
    int Bh = (B + 1) / 2;                          // elements per "lane 0"
    int Tdec_max = (B > 0) ? (out_size / (4 * B)) : 0;

    static bool attr_set = false;
    if (!attr_set) {
        cudaFuncSetAttribute(dynamics_kernel,
                             cudaFuncAttributeMaxDynamicSharedMemorySize, SMEM_BYTES);
        attr_set = true;
    }

    int grid = (Bh + THREADS - 1) / THREADS;       // 128 for B=65536
    dynamics_kernel<<<grid, THREADS, SMEM_BYTES>>>(
        poses, W_ih, W_hh, W_d, n_new, out, B, Bh, Tdec_max);
}